// round 9
// baseline (speedup 1.0000x reference)
#include <cuda_runtime.h>
#include <cuda_bf16.h>
#include <cuda_fp16.h>
#include <cstdint>
#include <math.h>

#define B_   2
#define S_   2048
#define NH   16
#define DK   64
#define HID  1024
#define ROWS (B_ * S_)          // 4096

static const size_t OUT_ELEMS = (size_t)ROWS * HID;   // 4,194,304

// ---------------------------------------------------------------------------
// Scratch (__device__ globals; no allocation allowed)
// ---------------------------------------------------------------------------
__device__ __nv_bfloat16 g_Xh [(size_t)ROWS * HID];
__device__ __nv_bfloat16 g_Xl [(size_t)ROWS * HID];
__device__ __nv_bfloat16 g_Wqh[(size_t)HID * HID];
__device__ __nv_bfloat16 g_Wql[(size_t)HID * HID];
__device__ __nv_bfloat16 g_Wkh[(size_t)HID * HID];
__device__ __nv_bfloat16 g_Wkl[(size_t)HID * HID];
__device__ __nv_bfloat16 g_Wvh[(size_t)HID * HID];
__device__ __nv_bfloat16 g_Woh[(size_t)HID * HID];
__device__ __half        g_Qf [(size_t)ROWS * HID];
__device__ __half        g_Kf [(size_t)ROWS * HID];
__device__ __nv_bfloat16 g_Vt16[(size_t)B_ * NH * DK * S_];          // [bh][d][k]
__device__ __nv_bfloat16 g_attn16[(size_t)B_ * NH * S_ * S_];        // 268 MB
__device__ __nv_bfloat16 g_ctx16[(size_t)ROWS * HID];
__device__ float         g_tmp [(size_t)ROWS * HID];

// Tile geometry: row = 72 halves (144 B) -> conflict-free ldmatrix phases.
#define TROW    72
#define TILE128 (128 * TROW * 2)   // 18432
#define TILE64  (64 * TROW * 2)    // 9216
#define SMEM_GEMM   (4 * TILE128)               // 73728: A0,A1,B0,B1
#define SMEM_CTX    (2 * TILE128 + 2 * TILE64)  // 55296
#define SMEM_SCORES (3 * TILE128)               // 55296: Q, K0, K1

// ---------------------------------------------------------------------------
// PTX helpers
// ---------------------------------------------------------------------------
__device__ __forceinline__ uint32_t smem_u32(const void* p) {
    uint32_t a;
    asm("{ .reg .u64 t; cvta.to.shared.u64 t, %1; cvt.u32.u64 %0, t; }"
        : "=r"(a) : "l"(p));
    return a;
}
__device__ __forceinline__ void cpa16(uint32_t dst, const void* src) {
    asm volatile("cp.async.cg.shared.global [%0], [%1], 16;"
                 :: "r"(dst), "l"(__cvta_generic_to_global(src)));
}
#define CPCOMMIT() asm volatile("cp.async.commit_group;" ::: "memory")
#define CPWAIT1()  asm volatile("cp.async.wait_group 1;" ::: "memory")
#define CPWAIT0()  asm volatile("cp.async.wait_group 0;" ::: "memory")

__device__ __forceinline__ void ldsm_x4(uint32_t (&r)[4], uint32_t addr) {
    asm volatile("ldmatrix.sync.aligned.m8n8.x4.shared.b16 {%0,%1,%2,%3}, [%4];"
                 : "=r"(r[0]), "=r"(r[1]), "=r"(r[2]), "=r"(r[3]) : "r"(addr));
}
__device__ __forceinline__ void mma_bf16(float (&c)[4], const uint32_t (&a)[4],
                                         uint32_t b0, uint32_t b1) {
    asm volatile(
        "mma.sync.aligned.m16n8k16.row.col.f32.bf16.bf16.f32 "
        "{%0,%1,%2,%3}, {%4,%5,%6,%7}, {%8,%9}, {%0,%1,%2,%3};"
        : "+f"(c[0]), "+f"(c[1]), "+f"(c[2]), "+f"(c[3])
        : "r"(a[0]), "r"(a[1]), "r"(a[2]), "r"(a[3]), "r"(b0), "r"(b1));
}
__device__ __forceinline__ void mma_f16(float (&c)[4], const uint32_t (&a)[4],
                                        uint32_t b0, uint32_t b1) {
    asm volatile(
        "mma.sync.aligned.m16n8k16.row.col.f32.f16.f16.f32 "
        "{%0,%1,%2,%3}, {%4,%5,%6,%7}, {%8,%9}, {%0,%1,%2,%3};"
        : "+f"(c[0]), "+f"(c[1]), "+f"(c[2]), "+f"(c[3])
        : "r"(a[0]), "r"(a[1]), "r"(a[2]), "r"(a[3]), "r"(b0), "r"(b1));
}

// One K-chunk of MMAs.
// SPLIT (bf16): cols [0..31]=hi, [32..63]=lo, 2 k16 steps, hi*hi+hi*lo+lo*hi.
// PLAIN: cols [0..63], 4 k16 steps, 1 term (bf16 or f16 via F16 flag).
template <int NT, bool SPLIT, bool F16>
__device__ __forceinline__ void mma_chunk(float (*cacc)[NT][4],
                                          const __nv_bfloat16 (*As)[TROW],
                                          const __nv_bfloat16 (*Bs)[TROW],
                                          int wm, int wn, int lane) {
    const int NS = SPLIT ? 2 : 4;
#pragma unroll
    for (int s = 0; s < NS; s++) {
        uint32_t ah[2][4], al[2][4];
#pragma unroll
        for (int mt = 0; mt < 2; mt++) {
            const int r = wm * 32 + mt * 16 + (lane & 15);
            const int cc = s * 16 + ((lane >> 4) << 3);
            ldsm_x4(ah[mt], smem_u32(&As[r][cc]));
            if (SPLIT) ldsm_x4(al[mt], smem_u32(&As[r][cc + 32]));
        }
#pragma unroll
        for (int g = 0; g < NT / 2; g++) {
            const int br = wn * (NT * 8) + g * 16 + (lane & 15);
            const int bc = s * 16 + ((lane >> 4) << 3);
            uint32_t bh[4], bl[4];
            ldsm_x4(bh, smem_u32(&Bs[br][bc]));
            if (SPLIT) ldsm_x4(bl, smem_u32(&Bs[br][bc + 32]));
#pragma unroll
            for (int mt = 0; mt < 2; mt++) {
                if (F16) {
                    mma_f16(cacc[mt][2 * g],     ah[mt], bh[0], bh[2]);
                    mma_f16(cacc[mt][2 * g + 1], ah[mt], bh[1], bh[3]);
                } else {
                    mma_bf16(cacc[mt][2 * g],     ah[mt], bh[0], bh[2]);
                    mma_bf16(cacc[mt][2 * g + 1], ah[mt], bh[1], bh[3]);
                }
                if (SPLIT) {
                    mma_bf16(cacc[mt][2 * g],     ah[mt], bl[0], bl[2]);
                    mma_bf16(cacc[mt][2 * g + 1], ah[mt], bl[1], bl[3]);
                    mma_bf16(cacc[mt][2 * g],     al[mt], bh[0], bh[2]);
                    mma_bf16(cacc[mt][2 * g + 1], al[mt], bh[1], bh[3]);
                }
            }
        }
    }
}

// ---------------------------------------------------------------------------
// Merged conversion kernel: X -> split, Wq/Wk -> split, Wv/Wo -> plain.
// ---------------------------------------------------------------------------
#define N_X4 (ROWS * HID / 4)      // 1,048,576
#define N_W4 (HID * HID / 4)       //   262,144

__device__ __forceinline__ void cvt4(const float* __restrict__ s, size_t i,
                                     __nv_bfloat16* __restrict__ dh,
                                     __nv_bfloat16* __restrict__ dl) {
    float4 v = ((const float4*)s)[i];
    __nv_bfloat16 h0 = __float2bfloat16(v.x), h1 = __float2bfloat16(v.y);
    __nv_bfloat16 h2 = __float2bfloat16(v.z), h3 = __float2bfloat16(v.w);
    uint2 hw;
    hw.x = (uint32_t)__bfloat16_as_ushort(h0) | ((uint32_t)__bfloat16_as_ushort(h1) << 16);
    hw.y = (uint32_t)__bfloat16_as_ushort(h2) | ((uint32_t)__bfloat16_as_ushort(h3) << 16);
    *(uint2*)(dh + i * 4) = hw;
    if (dl) {
        __nv_bfloat16 l0 = __float2bfloat16(v.x - __bfloat162float(h0));
        __nv_bfloat16 l1 = __float2bfloat16(v.y - __bfloat162float(h1));
        __nv_bfloat16 l2 = __float2bfloat16(v.z - __bfloat162float(h2));
        __nv_bfloat16 l3 = __float2bfloat16(v.w - __bfloat162float(h3));
        uint2 lw;
        lw.x = (uint32_t)__bfloat16_as_ushort(l0) | ((uint32_t)__bfloat16_as_ushort(l1) << 16);
        lw.y = (uint32_t)__bfloat16_as_ushort(l2) | ((uint32_t)__bfloat16_as_ushort(l3) << 16);
        *(uint2*)(dl + i * 4) = lw;
    }
}

__global__ __launch_bounds__(256) void k_cvt_all(const float* __restrict__ x,
                                                 const float* __restrict__ Wq,
                                                 const float* __restrict__ Wk,
                                                 const float* __restrict__ Wv,
                                                 const float* __restrict__ Wo) {
    const size_t i = (size_t)blockIdx.x * 256 + threadIdx.x;
    if (i < N_X4) {
        cvt4(x, i, g_Xh, g_Xl);
        return;
    }
    const size_t j = i - N_X4;
    const int w = (int)(j >> 18);        // N_W4 = 2^18
    const size_t k = j & (N_W4 - 1);
    if (w == 0)      cvt4(Wq, k, g_Wqh, g_Wql);
    else if (w == 1) cvt4(Wk, k, g_Wkh, g_Wkl);
    else if (w == 2) cvt4(Wv, k, g_Wvh, nullptr);
    else             cvt4(Wo, k, g_Woh, nullptr);
}

// ---------------------------------------------------------------------------
// Q/K projection (split-bf16 input): C = X @ W^T, epilogue -> fp16 Q/K.
// grid (8, 32, 2): z=0 -> Q, z=1 -> K.
// ---------------------------------------------------------------------------
__global__ __launch_bounds__(256) void k_proj_qk() {
    extern __shared__ __align__(16) char sm[];
    const int tid = threadIdx.x, lane = tid & 31, wid = tid >> 5;
    const int wm = wid & 3, wn = wid >> 2;
    const int z = blockIdx.z;
    const int rowBase = blockIdx.y * 128, colBase = blockIdx.x * 128;
    const __nv_bfloat16* Bh = z ? g_Wkh : g_Wqh;
    const __nv_bfloat16* Bl = z ? g_Wkl : g_Wql;
    __half* Of = z ? g_Kf : g_Qf;

    const int lrow = tid >> 1, hl = tid & 1;
    const __nv_bfloat16* asrc = (hl ? g_Xl : g_Xh) + (size_t)(rowBase + lrow) * HID;
    const __nv_bfloat16* bsrc = (hl ? Bl : Bh) + (size_t)(colBase + lrow) * HID;
    const uint32_t sb = smem_u32(sm);
    const uint32_t adst = sb + lrow * 144 + hl * 64;
    const uint32_t bdst = sb + 2 * TILE128 + lrow * 144 + hl * 64;

#pragma unroll
    for (int i = 0; i < 4; i++) {
        cpa16(adst + i * 16, asrc + i * 8);
        cpa16(bdst + i * 16, bsrc + i * 8);
    }
    CPCOMMIT();

    float c[2][8][4] = {};
    for (int ch = 0; ch < 32; ch++) {
        const int cur = ch & 1;
        if (ch < 31) {
            const int nb = cur ^ 1;
            const __nv_bfloat16* a = asrc + (ch + 1) * 32;
            const __nv_bfloat16* b = bsrc + (ch + 1) * 32;
#pragma unroll
            for (int i = 0; i < 4; i++) {
                cpa16(adst + nb * TILE128 + i * 16, a + i * 8);
                cpa16(bdst + nb * TILE128 + i * 16, b + i * 8);
            }
            CPCOMMIT();
            CPWAIT1();
        } else {
            CPWAIT0();
        }
        __syncthreads();
        mma_chunk<8, true, false>(c, (const __nv_bfloat16(*)[TROW])(sm + cur * TILE128),
                                  (const __nv_bfloat16(*)[TROW])(sm + (2 + cur) * TILE128),
                                  wm, wn, lane);
        __syncthreads();
    }
#pragma unroll
    for (int mt = 0; mt < 2; mt++) {
#pragma unroll
        for (int half = 0; half < 2; half++) {
            const int r = rowBase + wm * 32 + mt * 16 + (lane >> 2) + half * 8;
#pragma unroll
            for (int nt = 0; nt < 8; nt++) {
                const int cc = colBase + wn * 64 + nt * 8 + (lane & 3) * 2;
                __half h0 = __float2half(c[mt][nt][half * 2]);
                __half h1 = __float2half(c[mt][nt][half * 2 + 1]);
                uint32_t w = (uint32_t)__half_as_ushort(h0) |
                             ((uint32_t)__half_as_ushort(h1) << 16);
                *(uint32_t*)(Of + (size_t)r * HID + cc) = w;
            }
        }
    }
}

// ---------------------------------------------------------------------------
// V projection (plain bf16): V = X @ Wv^T, epilogue scatters into Vt16[bh][d][k]
// grid (8, 32)
// ---------------------------------------------------------------------------
__global__ __launch_bounds__(256) void k_proj_v() {
    extern __shared__ __align__(16) char sm[];
    const int tid = threadIdx.x, lane = tid & 31, wid = tid >> 5;
    const int wm = wid & 3, wn = wid >> 2;
    const int rowBase = blockIdx.y * 128, colBase = blockIdx.x * 128;

    const int lrow = tid >> 1, hf = tid & 1;
    const __nv_bfloat16* asrc = g_Xh + (size_t)(rowBase + lrow) * HID + hf * 32;
    const __nv_bfloat16* bsrc = g_Wvh + (size_t)(colBase + lrow) * HID + hf * 32;
    const uint32_t sb = smem_u32(sm);
    const uint32_t adst = sb + lrow * 144 + hf * 64;
    const uint32_t bdst = sb + 2 * TILE128 + lrow * 144 + hf * 64;

#pragma unroll
    for (int i = 0; i < 4; i++) {
        cpa16(adst + i * 16, asrc + i * 8);
        cpa16(bdst + i * 16, bsrc + i * 8);
    }
    CPCOMMIT();

    float c[2][8][4] = {};
    for (int ch = 0; ch < 16; ch++) {        // K = 1024, chunk 64
        const int cur = ch & 1;
        if (ch < 15) {
            const int nb = cur ^ 1;
            const __nv_bfloat16* a = asrc + (ch + 1) * 64;
            const __nv_bfloat16* b = bsrc + (ch + 1) * 64;
#pragma unroll
            for (int i = 0; i < 4; i++) {
                cpa16(adst + nb * TILE128 + i * 16, a + i * 8);
                cpa16(bdst + nb * TILE128 + i * 16, b + i * 8);
            }
            CPCOMMIT();
            CPWAIT1();
        } else {
            CPWAIT0();
        }
        __syncthreads();
        mma_chunk<8, false, false>(c, (const __nv_bfloat16(*)[TROW])(sm + cur * TILE128),
                                   (const __nv_bfloat16(*)[TROW])(sm + (2 + cur) * TILE128),
                                   wm, wn, lane);
        __syncthreads();
    }
    // scatter to Vt16[bh][d][k]
#pragma unroll
    for (int mt = 0; mt < 2; mt++) {
#pragma unroll
        for (int half = 0; half < 2; half++) {
            const int r = rowBase + wm * 32 + mt * 16 + (lane >> 2) + half * 8;
            const int b = r >> 11, k = r & (S_ - 1);
#pragma unroll
            for (int nt = 0; nt < 8; nt++) {
                const int cc = colBase + wn * 64 + nt * 8 + (lane & 3) * 2;
                const int h = cc >> 6, d = cc & 63;
                const size_t base = ((size_t)(b * NH + h) * DK + d) * S_ + k;
                g_Vt16[base]      = __float2bfloat16(c[mt][nt][half * 2]);
                g_Vt16[base + S_] = __float2bfloat16(c[mt][nt][half * 2 + 1]);
            }
        }
    }
}

// ---------------------------------------------------------------------------
// FUSED scores + softmax (two-pass online):
//   pass 0: MMA all 16 K-tiles, accumulate per-row online (max, sum)
//   reduce across quad lanes + paired warps
//   pass 1: re-MMA, write normalized fp32 attn + bf16 attn16
// grid (S_/128, B_*NH) = (16, 32), 256 threads.
// SMEM: [Q tile][K buf0][K buf1] = 3 * TILE128.
// ---------------------------------------------------------------------------
__global__ __launch_bounds__(256) void k_scores_softmax(const int* __restrict__ mask,
                                                        float* __restrict__ attn) {
    extern __shared__ __align__(16) char sm[];
    __shared__ float red[2][128][2];
    const int tid = threadIdx.x, lane = tid & 31, wid = tid >> 5;
    const int wm = wid & 3, wn = wid >> 2;
    const int bh = blockIdx.y, b = bh >> 4, h = bh & 15;
    const int rowBase = blockIdx.x * 128;

    const int lrow = tid >> 1, hf = tid & 1;
    const __half* qsrc = g_Qf + (size_t)(b * S_ + rowBase + lrow) * HID + h * DK + hf * 32;
    const __half* ksrc = g_Kf + (size_t)(b * S_ + lrow) * HID + h * DK + hf * 32;
    const uint32_t sb = smem_u32(sm);
    const uint32_t qdst = sb + lrow * 144 + hf * 64;
    const uint32_t kdst = sb + TILE128 + lrow * 144 + hf * 64;

    const int* mb = mask + (size_t)b * S_ * S_;
    float* ab = attn + (size_t)bh * S_ * S_;
    __nv_bfloat16* ab16 = g_attn16 + (size_t)bh * S_ * S_;

    float m[4], s[4], inv[4];
#pragma unroll
    for (int j = 0; j < 4; j++) { m[j] = -1e30f; s[j] = 0.f; inv[j] = 0.f; }

    // Q tile load (grouped with first K-tile commit)
#pragma unroll
    for (int i = 0; i < 4; i++) cpa16(qdst + i * 16, qsrc + i * 8);

    for (int pass = 0; pass < 2; pass++) {
        // preload K tile 0 into buf0
#pragma unroll
        for (int i = 0; i < 4; i++) cpa16(kdst + i * 16, ksrc + i * 8);
        CPCOMMIT();
        for (int t = 0; t < 16; t++) {
            const int cur = t & 1;
            if (t < 15) {
                const __half* kn = ksrc + (size_t)(t + 1) * 128 * HID;
                const uint32_t kd = kdst + (cur ^ 1) * TILE128;
#pragma unroll
                for (int i = 0; i < 4; i++) cpa16(kd + i * 16, kn + i * 8);
                CPCOMMIT();
                CPWAIT1();
            } else {
                CPWAIT0();
            }
            __syncthreads();
            float c[2][8][4] = {};
            mma_chunk<8, false, true>(c, (const __nv_bfloat16(*)[TROW])sm,
                                      (const __nv_bfloat16(*)[TROW])(sm + TILE128 + cur * TILE128),
                                      wm, wn, lane);
            const int colBase = t * 128;
            if (pass == 0) {
#pragma unroll
                for (int mt = 0; mt < 2; mt++)
#pragma unroll
                for (int half = 0; half < 2; half++) {
                    const int j = mt * 2 + half;
                    const int r = rowBase + wm * 32 + mt * 16 + (lane >> 2) + half * 8;
                    float ml = -1e30f;
#pragma unroll
                    for (int nt = 0; nt < 8; nt++) {
                        const int cc = colBase + wn * 64 + nt * 8 + (lane & 3) * 2;
                        int2 mk = *(const int2*)(mb + (size_t)r * S_ + cc);
                        float v0 = mk.x ? c[mt][nt][half * 2]     * 0.125f : -1e9f;
                        float v1 = mk.y ? c[mt][nt][half * 2 + 1] * 0.125f : -1e9f;
                        c[mt][nt][half * 2]     = v0;     // store masked value in place
                        c[mt][nt][half * 2 + 1] = v1;
                        ml = fmaxf(ml, fmaxf(v0, v1));
                    }
                    if (ml > m[j]) { s[j] *= __expf(m[j] - ml); m[j] = ml; }
                    float acc = 0.f;
#pragma unroll
                    for (int nt = 0; nt < 8; nt++)
                        acc += __expf(c[mt][nt][half * 2] - m[j]) +
                               __expf(c[mt][nt][half * 2 + 1] - m[j]);
                    s[j] += acc;
                }
            } else {
#pragma unroll
                for (int mt = 0; mt < 2; mt++)
#pragma unroll
                for (int half = 0; half < 2; half++) {
                    const int j = mt * 2 + half;
                    const int r = rowBase + wm * 32 + mt * 16 + (lane >> 2) + half * 8;
#pragma unroll
                    for (int nt = 0; nt < 8; nt++) {
                        const int cc = colBase + wn * 64 + nt * 8 + (lane & 3) * 2;
                        int2 mk = *(const int2*)(mb + (size_t)r * S_ + cc);
                        float v0 = mk.x ? c[mt][nt][half * 2]     * 0.125f : -1e9f;
                        float v1 = mk.y ? c[mt][nt][half * 2 + 1] * 0.125f : -1e9f;
                        float o0 = __expf(v0 - m[j]) * inv[j];
                        float o1 = __expf(v1 - m[j]) * inv[j];
                        *(float2*)(ab + (size_t)r * S_ + cc) = make_float2(o0, o1);
                        uint32_t w = (uint32_t)__bfloat16_as_ushort(__float2bfloat16(o0)) |
                                     ((uint32_t)__bfloat16_as_ushort(__float2bfloat16(o1)) << 16);
                        *(uint32_t*)(ab16 + (size_t)r * S_ + cc) = w;
                    }
                }
            }
            __syncthreads();
        }
        if (pass == 0) {
            // combine (m, s) across the 4 lanes of each quad
#pragma unroll
            for (int j = 0; j < 4; j++) {
#pragma unroll
                for (int off = 1; off <= 2; off <<= 1) {
                    float mo = __shfl_xor_sync(0xffffffffu, m[j], off);
                    float so = __shfl_xor_sync(0xffffffffu, s[j], off);
                    float mn = fmaxf(m[j], mo);
                    s[j] = s[j] * __expf(m[j] - mn) + so * __expf(mo - mn);
                    m[j] = mn;
                }
            }
            // combine across the two wn warps via smem
            if ((lane & 3) == 0) {
#pragma unroll
                for (int j = 0; j < 4; j++) {
                    const int mt = j >> 1, half = j & 1;
                    const int rl = wm * 32 + mt * 16 + (lane >> 2) + half * 8;
                    red[wn][rl][0] = m[j];
                    red[wn][rl][1] = s[j];
                }
            }
            __syncthreads();
#pragma unroll
            for (int j = 0; j < 4; j++) {
                const int mt = j >> 1, half = j & 1;
                const int rl = wm * 32 + mt * 16 + (lane >> 2) + half * 8;
                float mo = red[wn ^ 1][rl][0];
                float so = red[wn ^ 1][rl][1];
                float mn = fmaxf(m[j], mo);
                s[j] = s[j] * __expf(m[j] - mn) + so * __expf(mo - mn);
                m[j] = mn;
                inv[j] = 1.0f / s[j];
            }
        }
    }
}

// ---------------------------------------------------------------------------
// Context (plain bf16): ctx[q,d] = sum_k attn16[q,k] * Vt16[bh][d][k]. grid (16,1,32)
// ---------------------------------------------------------------------------
__global__ __launch_bounds__(256) void k_context() {
    extern __shared__ __align__(16) char sm[];
    const int tid = threadIdx.x, lane = tid & 31, wid = tid >> 5;
    const int wm = wid & 3, wn = wid >> 2;
    const int bh = blockIdx.z, b = bh >> 4, h = bh & 15;
    const int rowBase = blockIdx.x * 128;

    const int lrow = tid >> 1, hf = tid & 1;
    const int bd = tid >> 2, bq = tid & 3;
    const __nv_bfloat16* asrc = g_attn16
        + ((size_t)bh * S_ + rowBase + lrow) * S_ + hf * 32;
    const __nv_bfloat16* bsrc = g_Vt16 + ((size_t)bh * DK + bd) * S_ + bq * 16;
    const uint32_t sb = smem_u32(sm);
    const uint32_t adst = sb + lrow * 144 + hf * 64;
    const uint32_t bdst = sb + 2 * TILE128 + bd * 144 + bq * 32;

#pragma unroll
    for (int i = 0; i < 4; i++) cpa16(adst + i * 16, asrc + i * 8);
    cpa16(bdst, bsrc);
    cpa16(bdst + 16, bsrc + 8);
    CPCOMMIT();

    float c[2][4][4] = {};
    for (int ch = 0; ch < 32; ch++) {        // K = 2048, chunk 64
        const int cur = ch & 1;
        if (ch < 31) {
            const int nb = cur ^ 1;
            const __nv_bfloat16* a = asrc + (ch + 1) * 64;
            const __nv_bfloat16* bb = bsrc + (ch + 1) * 64;
#pragma unroll
            for (int i = 0; i < 4; i++) cpa16(adst + nb * TILE128 + i * 16, a + i * 8);
            cpa16(bdst + nb * TILE64, bb);
            cpa16(bdst + nb * TILE64 + 16, bb + 8);
            CPCOMMIT();
            CPWAIT1();
        } else {
            CPWAIT0();
        }
        __syncthreads();
        mma_chunk<4, false, false>(c, (const __nv_bfloat16(*)[TROW])(sm + cur * TILE128),
                                   (const __nv_bfloat16(*)[TROW])(sm + 2 * TILE128 + cur * TILE64),
                                   wm, wn, lane);
        __syncthreads();
    }
#pragma unroll
    for (int mt = 0; mt < 2; mt++) {
#pragma unroll
        for (int half = 0; half < 2; half++) {
            const int q = rowBase + wm * 32 + mt * 16 + (lane >> 2) + half * 8;
#pragma unroll
            for (int nt = 0; nt < 4; nt++) {
                const int d = wn * 32 + nt * 8 + (lane & 3) * 2;
                __nv_bfloat16 v0 = __float2bfloat16(c[mt][nt][half * 2]);
                __nv_bfloat16 v1 = __float2bfloat16(c[mt][nt][half * 2 + 1]);
                uint32_t w = (uint32_t)__bfloat16_as_ushort(v0) |
                             ((uint32_t)__bfloat16_as_ushort(v1) << 16);
                *(uint32_t*)(g_ctx16 + ((size_t)b * S_ + q) * HID + h * DK + d) = w;
            }
        }
    }
}

// ---------------------------------------------------------------------------
// O projection (plain bf16) + residual: tmp = ctx16 @ Wo16^T + x.  grid (8, 32)
// ---------------------------------------------------------------------------
__global__ __launch_bounds__(256) void k_oproj(const float* __restrict__ x) {
    extern __shared__ __align__(16) char sm[];
    const int tid = threadIdx.x, lane = tid & 31, wid = tid >> 5;
    const int wm = wid & 3, wn = wid >> 2;
    const int rowBase = blockIdx.y * 128, colBase = blockIdx.x * 128;

    const int lrow = tid >> 1, hf = tid & 1;
    const __nv_bfloat16* asrc = g_ctx16 + (size_t)(rowBase + lrow) * HID + hf * 32;
    const __nv_bfloat16* bsrc = g_Woh + (size_t)(colBase + lrow) * HID + hf * 32;
    const uint32_t sb = smem_u32(sm);
    const uint32_t adst = sb + lrow * 144 + hf * 64;
    const uint32_t bdst = sb + 2 * TILE128 + lrow * 144 + hf * 64;

#pragma unroll
    for (int i = 0; i < 4; i++) {
        cpa16(adst + i * 16, asrc + i * 8);
        cpa16(bdst + i * 16, bsrc + i * 8);
    }
    CPCOMMIT();

    float c[2][8][4] = {};
    for (int ch = 0; ch < 16; ch++) {        // K = 1024, chunk 64
        const int cur = ch & 1;
        if (ch < 15) {
            const int nb = cur ^ 1;
            const __nv_bfloat16* a = asrc + (ch + 1) * 64;
            const __nv_bfloat16* b = bsrc + (ch + 1) * 64;
#pragma unroll
            for (int i = 0; i < 4; i++) {
                cpa16(adst + nb * TILE128 + i * 16, a + i * 8);
                cpa16(bdst + nb * TILE128 + i * 16, b + i * 8);
            }
            CPCOMMIT();
            CPWAIT1();
        } else {
            CPWAIT0();
        }
        __syncthreads();
        mma_chunk<8, false, false>(c, (const __nv_bfloat16(*)[TROW])(sm + cur * TILE128),
                                   (const __nv_bfloat16(*)[TROW])(sm + (2 + cur) * TILE128),
                                   wm, wn, lane);
        __syncthreads();
    }
#pragma unroll
    for (int mt = 0; mt < 2; mt++) {
#pragma unroll
        for (int half = 0; half < 2; half++) {
            const int r = rowBase + wm * 32 + mt * 16 + (lane >> 2) + half * 8;
#pragma unroll
            for (int nt = 0; nt < 8; nt++) {
                const int cc = colBase + wn * 64 + nt * 8 + (lane & 3) * 2;
                float2 q = *(const float2*)(x + (size_t)r * HID + cc);
                float2 v = make_float2(c[mt][nt][half * 2] + q.x,
                                       c[mt][nt][half * 2 + 1] + q.y);
                *(float2*)(g_tmp + (size_t)r * HID + cc) = v;
            }
        }
    }
}

// ---------------------------------------------------------------------------
// LayerNorm
// ---------------------------------------------------------------------------
__device__ __forceinline__ float blockReduceSum(float v) {
    __shared__ float s[8];
    const int lane = threadIdx.x & 31, wid = threadIdx.x >> 5;
#pragma unroll
    for (int o = 16; o > 0; o >>= 1) v += __shfl_xor_sync(0xffffffffu, v, o);
    __syncthreads();
    if (lane == 0) s[wid] = v;
    __syncthreads();
    float r = s[0];
#pragma unroll
    for (int i = 1; i < 8; i++) r += s[i];
    return r;
}

__global__ __launch_bounds__(256) void ln_kernel(const float* __restrict__ x,
                                                 float* __restrict__ out) {
    const size_t row = blockIdx.x;
    const float4* p = (const float4*)(x + row * HID);
    const int tid = threadIdx.x;
    float4 v = p[tid];
    float s = v.x + v.y + v.z + v.w;
    s = blockReduceSum(s);
    const float mu = s * (1.0f / HID);
    float dx = v.x - mu, dy = v.y - mu, dz = v.z - mu, dw = v.w - mu;
    float sq = dx * dx + dy * dy + dz * dz + dw * dw;
    sq = blockReduceSum(sq);
    const float inv = rsqrtf(sq * (1.0f / HID) + 1e-5f);
    float4 o;
    o.x = dx * inv; o.y = dy * inv; o.z = dz * inv; o.w = dw * inv;
    ((float4*)(out + row * HID))[tid] = o;
}

// ===========================================================================
extern "C" void kernel_launch(void* const* d_in, const int* in_sizes, int n_in,
                              void* d_out, int out_size)
{
    (void)in_sizes; (void)n_in; (void)out_size;
    const float* x  = (const float*)d_in[0];
    const int* mask = (const int*)d_in[1];
    const float* Wq = (const float*)d_in[2];
    const float* Wk = (const float*)d_in[3];
    const float* Wv = (const float*)d_in[4];
    const float* Wo = (const float*)d_in[5];
    float* out  = (float*)d_out;
    float* attn = out + OUT_ELEMS;

    float* ptmp;
    cudaGetSymbolAddress((void**)&ptmp, g_tmp);

    cudaFuncSetAttribute(k_proj_qk, cudaFuncAttributeMaxDynamicSharedMemorySize, SMEM_GEMM);
    cudaFuncSetAttribute(k_proj_v,  cudaFuncAttributeMaxDynamicSharedMemorySize, SMEM_GEMM);
    cudaFuncSetAttribute(k_scores_softmax, cudaFuncAttributeMaxDynamicSharedMemorySize, SMEM_SCORES);
    cudaFuncSetAttribute(k_context, cudaFuncAttributeMaxDynamicSharedMemorySize, SMEM_CTX);
    cudaFuncSetAttribute(k_oproj,   cudaFuncAttributeMaxDynamicSharedMemorySize, SMEM_GEMM);

    dim3 blk(256);

    // Merged pre-conversions (X split, Wq/Wk split, Wv/Wo plain)
    k_cvt_all<<<dim3((N_X4 + 4 * N_W4) / 256), blk>>>(x, Wq, Wk, Wv, Wo);

    // Projections
    k_proj_qk<<<dim3(HID / 128, ROWS / 128, 2), blk, SMEM_GEMM>>>();
    k_proj_v <<<dim3(HID / 128, ROWS / 128),    blk, SMEM_GEMM>>>();

    // Fused scores + softmax -> fp32 attn + bf16 attn16
    k_scores_softmax<<<dim3(S_ / 128, B_ * NH), blk, SMEM_SCORES>>>(mask, attn);

    // Context
    k_context<<<dim3(S_ / 128, 1, B_ * NH), blk, SMEM_CTX>>>();

    // O projection + residual
    k_oproj<<<dim3(HID / 128, ROWS / 128), blk, SMEM_GEMM>>>(x);

    // LayerNorm
    ln_kernel<<<dim3(ROWS), blk>>>(ptmp, out);
}